// round 4
// baseline (speedup 1.0000x reference)
#include <cuda_runtime.h>
#include <cuda_bf16.h>
#include <math.h>

// Problem constants (fixed by setup_inputs)
#define BATCH  4
#define LSEQ   2048
#define DMODEL 2048
#define HID    2048
#define NH     32
#define DHEAD  64
#define WIN    64
#define NB     (LSEQ / WIN)      // 32
#define SINKS  16
#define NKEY   (SINKS + 3 * WIN) // 208
#define TPAD   68                // padded row stride for Q/K/V tiles (floats)
#define PPAD   209               // padded row stride for P tile (floats)

// Scratch (allocation-free: __device__ globals)
__device__ float g_qkv[(size_t)BATCH * LSEQ * 3 * HID];   // [B*L, 3H]
__device__ float g_att[(size_t)BATCH * LSEQ * HID];       // [B*L, H]

// ---------------------------------------------------------------------------
// C[m,n] = sum_k A[m,k] * W[n,k] + bias[n]   (A row-major, W row-major)
// Tiles: 128x128x16, 256 threads, 8x8 per thread.
// Register prefetch (LDG for tile k+1 overlaps FFMAs of tile k) plus
// double-buffered smem: exactly ONE __syncthreads per k-iteration.
// Requires M%128==0, N%128==0, K%16==0 (true for all shapes here).
// ---------------------------------------------------------------------------
__global__ void __launch_bounds__(256) sgemm_nt_bias(
    const float* __restrict__ A, const float* __restrict__ W,
    const float* __restrict__ bias, float* __restrict__ C,
    int M, int N, int K)
{
    __shared__ float As[2][16][128];
    __shared__ float Bs[2][16][128];

    const int tid = threadIdx.x;
    const int bm = blockIdx.y * 128;
    const int bn = blockIdx.x * 128;
    const int ty = tid >> 4;       // 0..15
    const int tx = tid & 15;       // 0..15

    // fixed per-thread load coordinates (2 float4 per matrix per stage)
    int lrow[2], lkq[2];
#pragma unroll
    for (int p = 0; p < 2; ++p) {
        int f = tid + p * 256;     // 0..511
        lrow[p] = f >> 2;          // 0..127
        lkq[p]  = f & 3;           // 0..3
    }

    float acc[8][8];
#pragma unroll
    for (int i = 0; i < 8; ++i)
#pragma unroll
        for (int j = 0; j < 8; ++j) acc[i][j] = 0.f;

    float4 pa[2], pw[2];
    // prologue: load tile 0 into registers
#pragma unroll
    for (int p = 0; p < 2; ++p) {
        pa[p] = *(const float4*)(A + (size_t)(bm + lrow[p]) * K + lkq[p] * 4);
        pw[p] = *(const float4*)(W + (size_t)(bn + lrow[p]) * K + lkq[p] * 4);
    }

    int buf = 0;
    for (int k0 = 0; k0 < K; k0 += 16, buf ^= 1) {
        // store current tile (registers -> smem[buf], transposed to k-major)
#pragma unroll
        for (int p = 0; p < 2; ++p) {
            int row = lrow[p], kq = lkq[p];
            As[buf][kq * 4 + 0][row] = pa[p].x;
            As[buf][kq * 4 + 1][row] = pa[p].y;
            As[buf][kq * 4 + 2][row] = pa[p].z;
            As[buf][kq * 4 + 3][row] = pa[p].w;
            Bs[buf][kq * 4 + 0][row] = pw[p].x;
            Bs[buf][kq * 4 + 1][row] = pw[p].y;
            Bs[buf][kq * 4 + 2][row] = pw[p].z;
            Bs[buf][kq * 4 + 3][row] = pw[p].w;
        }
        __syncthreads();   // single barrier per iteration (double-buffered)

        // prefetch next tile into registers (overlaps with FFMA loop below)
        if (k0 + 16 < K) {
#pragma unroll
            for (int p = 0; p < 2; ++p) {
                pa[p] = *(const float4*)(A + (size_t)(bm + lrow[p]) * K + k0 + 16 + lkq[p] * 4);
                pw[p] = *(const float4*)(W + (size_t)(bn + lrow[p]) * K + k0 + 16 + lkq[p] * 4);
            }
        }

#pragma unroll
        for (int kk = 0; kk < 16; ++kk) {
            float a[8], b[8];
            *(float4*)(a)     = *(const float4*)&As[buf][kk][ty * 8];
            *(float4*)(a + 4) = *(const float4*)&As[buf][kk][ty * 8 + 4];
            *(float4*)(b)     = *(const float4*)&Bs[buf][kk][tx * 8];
            *(float4*)(b + 4) = *(const float4*)&Bs[buf][kk][tx * 8 + 4];
#pragma unroll
            for (int i = 0; i < 8; ++i)
#pragma unroll
                for (int j = 0; j < 8; ++j)
                    acc[i][j] += a[i] * b[j];
        }
    }

    // epilogue
#pragma unroll
    for (int i = 0; i < 8; ++i) {
        size_t crow = (size_t)(bm + ty * 8 + i) * N + bn + tx * 8;
#pragma unroll
        for (int j = 0; j < 8; j += 4) {
            float4 o;
            o.x = acc[i][j + 0] + bias[bn + tx * 8 + j + 0];
            o.y = acc[i][j + 1] + bias[bn + tx * 8 + j + 1];
            o.z = acc[i][j + 2] + bias[bn + tx * 8 + j + 2];
            o.w = acc[i][j + 3] + bias[bn + tx * 8 + j + 3];
            *(float4*)(C + crow + j) = o;
        }
    }
}

// ---------------------------------------------------------------------------
// Attention: one block per (window n, head h, batch b). 256 threads.
// Shared layout (floats):
//   Qs[64][TPAD]  : RoPE'd, pre-scaled Q
//   Ts[208][TPAD] : rows 0..15 = sinks, 16..207 = RoPE'd K band; later V band
//   Ps[64][PPAD]  : scores -> probabilities
// ---------------------------------------------------------------------------
__device__ __forceinline__ float rope_inv_freq(int j) {
    // 10000^(-j/32), computed in double then rounded (matches fp32 ref within tol)
    return (float)exp2(-(double)j * (13.287712379549449 / 32.0));
}

__global__ void __launch_bounds__(256) attn_kernel(
    const float* __restrict__ qkv,    // [B*L, 3H]
    const float* __restrict__ sinks,  // [NH, SINKS, DHEAD]
    float* __restrict__ Oout)         // [B*L, H]
{
    extern __shared__ float sm[];
    float* Qs = sm;                       // 64*TPAD
    float* Ts = sm + 64 * TPAD;           // 208*TPAD
    float* Ps = Ts + NKEY * TPAD;         // 64*PPAD

    const int n = blockIdx.x;
    const int h = blockIdx.y;
    const int b = blockIdx.z;
    const int tid = threadIdx.x;
    const float scale = 0.125f;           // 1/sqrt(64)

    // ---- load Q (RoPE + scale) ----
    for (int idx = tid; idx < 64 * 64; idx += 256) {
        int r  = idx >> 6;
        int dd = idx & 63;
        int l  = n * WIN + r;
        const float* qrow = qkv + (size_t)(b * LSEQ + l) * (3 * HID) + h * DHEAD;
        int j = dd & 31;
        float ang = (float)l * rope_inv_freq(j);
        float s, c;
        sincosf(ang, &s, &c);
        float x1 = qrow[j];
        float x2 = qrow[j + 32];
        float val = (dd < 32) ? (x1 * c - x2 * s) : (x1 * s + x2 * c);
        Qs[r * TPAD + dd] = val * scale;
    }
    // ---- sinks into Ts rows 0..15 ----
    for (int idx = tid; idx < SINKS * 64; idx += 256) {
        int r  = idx >> 6;
        int dd = idx & 63;
        Ts[r * TPAD + dd] = sinks[((size_t)h * SINKS + r) * DHEAD + dd];
    }
    // ---- K band (RoPE) into Ts rows 16..207 ----
    for (int idx = tid; idx < 3 * WIN * 64; idx += 256) {
        int kk = idx >> 6;          // 0..191
        int dd = idx & 63;
        int bn = n - 1 + kk / WIN;
        float val = 0.f;
        if (bn >= 0 && bn < NB) {
            int lk = bn * WIN + (kk & (WIN - 1));
            const float* krow = qkv + (size_t)(b * LSEQ + lk) * (3 * HID) + HID + h * DHEAD;
            int j = dd & 31;
            float ang = (float)lk * rope_inv_freq(j);
            float s, c;
            sincosf(ang, &s, &c);
            float x1 = krow[j];
            float x2 = krow[j + 32];
            val = (dd < 32) ? (x1 * c - x2 * s) : (x1 * s + x2 * c);
        }
        Ts[(SINKS + kk) * TPAD + dd] = val;
    }
    __syncthreads();

    // ---- scores: thread (qr, part) computes keys kk = part + 4*i ----
    const int qr   = tid >> 2;
    const int part = tid & 3;
    const int lq   = n * WIN + qr;
    const float* qrowS = Qs + qr * TPAD;

    for (int i = 0; i < NKEY / 4; ++i) {
        int kk = part + 4 * i;
        const float* trow = Ts + kk * TPAD;
        float s = 0.f;
#pragma unroll
        for (int d4 = 0; d4 < 16; ++d4) {
            float4 qv = *(const float4*)(qrowS + d4 * 4);
            float4 tv = *(const float4*)(trow + d4 * 4);
            s += qv.x * tv.x + qv.y * tv.y + qv.z * tv.z + qv.w * tv.w;
        }
        bool valid = true;
        if (kk >= SINKS) {
            int kb = kk - SINKS;
            int bn = n - 1 + kb / WIN;
            int lk = bn * WIN + (kb & (WIN - 1));
            valid = (bn >= 0) && (bn < NB) && (abs(lq - lk) <= WIN);
        }
        Ps[qr * PPAD + kk] = valid ? s : -1e30f;
    }

    // ---- softmax per row: 4 lanes per row, quad-aligned within warp ----
    float mx = -1e30f;
    for (int i = 0; i < NKEY / 4; ++i)
        mx = fmaxf(mx, Ps[qr * PPAD + part + 4 * i]);
    mx = fmaxf(mx, __shfl_xor_sync(0xffffffffu, mx, 1));
    mx = fmaxf(mx, __shfl_xor_sync(0xffffffffu, mx, 2));
    float sum = 0.f;
    for (int i = 0; i < NKEY / 4; ++i) {
        float e = __expf(Ps[qr * PPAD + part + 4 * i] - mx);
        Ps[qr * PPAD + part + 4 * i] = e;
        sum += e;
    }
    sum += __shfl_xor_sync(0xffffffffu, sum, 1);
    sum += __shfl_xor_sync(0xffffffffu, sum, 2);
    float inv = 1.f / sum;
    for (int i = 0; i < NKEY / 4; ++i)
        Ps[qr * PPAD + part + 4 * i] *= inv;

    __syncthreads();  // all scores done; safe to overwrite Ts with V

    // ---- V band into Ts rows 16..207 (sinks rows already hold sink values) ----
    for (int idx = tid; idx < 3 * WIN * 64; idx += 256) {
        int kk = idx >> 6;
        int dd = idx & 63;
        int bn = n - 1 + kk / WIN;
        float v = 0.f;
        if (bn >= 0 && bn < NB) {
            int lk = bn * WIN + (kk & (WIN - 1));
            v = qkv[(size_t)(b * LSEQ + lk) * (3 * HID) + 2 * HID + h * DHEAD + dd];
        }
        Ts[(SINKS + kk) * TPAD + dd] = v;
    }
    __syncthreads();

    // ---- O = P @ [sinks; Vband] : thread (qr, part) owns dims part*16..+15 ----
    const int dseg = part * 16;
    float accv[16];
#pragma unroll
    for (int j = 0; j < 16; ++j) accv[j] = 0.f;

    for (int k = 0; k < NKEY; ++k) {
        float p = Ps[qr * PPAD + k];
        const float* vrow = Ts + k * TPAD + dseg;
#pragma unroll
        for (int j4 = 0; j4 < 4; ++j4) {
            float4 vv = *(const float4*)(vrow + j4 * 4);
            accv[j4 * 4 + 0] += p * vv.x;
            accv[j4 * 4 + 1] += p * vv.y;
            accv[j4 * 4 + 2] += p * vv.z;
            accv[j4 * 4 + 3] += p * vv.w;
        }
    }

    float* orow = Oout + (size_t)(b * LSEQ + lq) * HID + h * DHEAD + dseg;
#pragma unroll
    for (int j4 = 0; j4 < 4; ++j4) {
        float4 o;
        o.x = accv[j4 * 4 + 0];
        o.y = accv[j4 * 4 + 1];
        o.z = accv[j4 * 4 + 2];
        o.w = accv[j4 * 4 + 3];
        *(float4*)(orow + j4 * 4) = o;
    }
}

// ---------------------------------------------------------------------------
extern "C" void kernel_launch(void* const* d_in, const int* in_sizes, int n_in,
                              void* d_out, int out_size)
{
    const float* u     = (const float*)d_in[0];  // [B, L, D]
    const float* Wqkv  = (const float*)d_in[1];  // [3H, D]
    const float* bqkv  = (const float*)d_in[2];  // [3H]
    const float* Wo    = (const float*)d_in[3];  // [D, H]
    const float* bo    = (const float*)d_in[4];  // [D]
    const float* sinks = (const float*)d_in[5];  // [NH, S, DHEAD]
    float* y = (float*)d_out;                    // [B, L, D]

    void* p;
    cudaGetSymbolAddress(&p, g_qkv);
    float* qkv = (float*)p;
    cudaGetSymbolAddress(&p, g_att);
    float* att = (float*)p;

    const int M = BATCH * LSEQ;   // 8192

    // 1) qkv = u @ Wqkv^T + bqkv     [8192, 6144]
    {
        dim3 grid(3 * HID / 128, M / 128);
        sgemm_nt_bias<<<grid, 256>>>(u, Wqkv, bqkv, qkv, M, 3 * HID, DMODEL);
    }

    // 2) attention (RoPE fused)
    {
        const int smem = (64 * TPAD + NKEY * TPAD + 64 * PPAD) * (int)sizeof(float); // 127488
        cudaFuncSetAttribute(attn_kernel, cudaFuncAttributeMaxDynamicSharedMemorySize, smem);
        dim3 grid(NB, NH, BATCH);
        attn_kernel<<<grid, 256, smem>>>(qkv, sinks, att);
    }

    // 3) y = att @ Wo^T + bo         [8192, 2048]
    {
        dim3 grid(DMODEL / 128, M / 128);
        sgemm_nt_bias<<<grid, 256>>>(att, Wo, bo, y, M, DMODEL, HID);
    }
}

// round 7
// speedup vs baseline: 1.8445x; 1.8445x over previous
#include <cuda_runtime.h>
#include <cuda_bf16.h>
#include <math.h>

// Problem constants (fixed by setup_inputs)
#define BATCH  4
#define LSEQ   2048
#define DMODEL 2048
#define HID    2048
#define NH     32
#define DHEAD  64
#define WIN    64
#define NB     (LSEQ / WIN)      // 32
#define SINKS  16
#define NKEY   (SINKS + 3 * WIN) // 208
#define TPAD   68
#define PPAD   209
#define SMS    136               // smem row stride (floats) for GEMM tiles

// Scratch (allocation-free: __device__ globals)
__device__ float g_qkv[(size_t)BATCH * LSEQ * 3 * HID];   // [B*L, 3H]
__device__ float g_att[(size_t)BATCH * LSEQ * HID];       // [B*L, H]

__device__ __forceinline__ unsigned f2tf32(float x) {
    unsigned u;
    asm("cvt.rna.tf32.f32 %0, %1;" : "=r"(u) : "f"(x));
    return u;
}

__device__ __forceinline__ void mma_tf32(float c[4], const unsigned a[4],
                                         const unsigned b[2]) {
    asm volatile(
        "mma.sync.aligned.m16n8k8.row.col.f32.tf32.tf32.f32 "
        "{%0,%1,%2,%3}, {%4,%5,%6,%7}, {%8,%9}, {%0,%1,%2,%3};\n"
        : "+f"(c[0]), "+f"(c[1]), "+f"(c[2]), "+f"(c[3])
        : "r"(a[0]), "r"(a[1]), "r"(a[2]), "r"(a[3]), "r"(b[0]), "r"(b[1]));
}

// ---------------------------------------------------------------------------
// C[m,n] = sum_k A[m,k] * W[n,k] + bias[n]   via TF32 tensor cores.
// Tiles: 128x128x16, 256 threads (8 warps), warp computes 64x32.
// Register prefetch + double-buffered smem (1 barrier per k-iter).
// Smem k-major with stride SMS=136 -> conflict-free fragment LDS.
// ---------------------------------------------------------------------------
__global__ void __launch_bounds__(256) tf32gemm_nt_bias(
    const float* __restrict__ A, const float* __restrict__ W,
    const float* __restrict__ bias, float* __restrict__ C,
    int M, int N, int K)
{
    __shared__ unsigned As[2][16 * SMS];
    __shared__ unsigned Bs[2][16 * SMS];

    const int tid  = threadIdx.x;
    const int warp = tid >> 5;
    const int lane = tid & 31;
    const int lr   = lane >> 2;   // 0..7
    const int lq   = lane & 3;    // 0..3
    const int wm   = warp >> 2;   // 0..1 : m-half (64 rows)
    const int wn   = warp & 3;    // 0..3 : n-quarter (32 cols)

    const int bm = blockIdx.y * 128;
    const int bn = blockIdx.x * 128;

    // per-thread global load coordinates (2 float4 per matrix per tile)
    int lrow[2], lkq[2];
#pragma unroll
    for (int p = 0; p < 2; ++p) {
        int f = tid + p * 256;
        lrow[p] = f >> 2;          // 0..127
        lkq[p]  = f & 3;           // 0..3
    }

    float acc[16][4];
#pragma unroll
    for (int i = 0; i < 16; ++i)
#pragma unroll
        for (int j = 0; j < 4; ++j) acc[i][j] = 0.f;

    float4 pa[2], pw[2];
#pragma unroll
    for (int p = 0; p < 2; ++p) {
        pa[p] = *(const float4*)(A + (size_t)(bm + lrow[p]) * K + lkq[p] * 4);
        pw[p] = *(const float4*)(W + (size_t)(bn + lrow[p]) * K + lkq[p] * 4);
    }

    int buf = 0;
    for (int k0 = 0; k0 < K; k0 += 16, buf ^= 1) {
        // store current tile (convert f32 -> tf32 at STS)
#pragma unroll
        for (int p = 0; p < 2; ++p) {
            int row = lrow[p], kq = lkq[p];
            As[buf][(kq * 4 + 0) * SMS + row] = f2tf32(pa[p].x);
            As[buf][(kq * 4 + 1) * SMS + row] = f2tf32(pa[p].y);
            As[buf][(kq * 4 + 2) * SMS + row] = f2tf32(pa[p].z);
            As[buf][(kq * 4 + 3) * SMS + row] = f2tf32(pa[p].w);
            Bs[buf][(kq * 4 + 0) * SMS + row] = f2tf32(pw[p].x);
            Bs[buf][(kq * 4 + 1) * SMS + row] = f2tf32(pw[p].y);
            Bs[buf][(kq * 4 + 2) * SMS + row] = f2tf32(pw[p].z);
            Bs[buf][(kq * 4 + 3) * SMS + row] = f2tf32(pw[p].w);
        }
        __syncthreads();

        // prefetch next tile (overlaps with MMAs)
        if (k0 + 16 < K) {
#pragma unroll
            for (int p = 0; p < 2; ++p) {
                pa[p] = *(const float4*)(A + (size_t)(bm + lrow[p]) * K + k0 + 16 + lkq[p] * 4);
                pw[p] = *(const float4*)(W + (size_t)(bn + lrow[p]) * K + k0 + 16 + lkq[p] * 4);
            }
        }

#pragma unroll
        for (int ks = 0; ks < 2; ++ks) {           // two k=8 steps per tile
            const int kk = ks * 8;
            unsigned a[4][4], b[4][2];
#pragma unroll
            for (int mt = 0; mt < 4; ++mt) {
                int m0 = wm * 64 + mt * 16;
                a[mt][0] = As[buf][(kk + lq)     * SMS + m0 + lr];
                a[mt][1] = As[buf][(kk + lq)     * SMS + m0 + lr + 8];
                a[mt][2] = As[buf][(kk + lq + 4) * SMS + m0 + lr];
                a[mt][3] = As[buf][(kk + lq + 4) * SMS + m0 + lr + 8];
            }
#pragma unroll
            for (int nt = 0; nt < 4; ++nt) {
                int n0 = wn * 32 + nt * 8;
                b[nt][0] = Bs[buf][(kk + lq)     * SMS + n0 + lr];
                b[nt][1] = Bs[buf][(kk + lq + 4) * SMS + n0 + lr];
            }
#pragma unroll
            for (int mt = 0; mt < 4; ++mt)
#pragma unroll
                for (int nt = 0; nt < 4; ++nt)
                    mma_tf32(acc[mt * 4 + nt], a[mt], b[nt]);
        }
        __syncthreads();
    }

    // epilogue: c0 (lr, 2lq), c1 (lr, 2lq+1), c2 (lr+8, 2lq), c3 (lr+8, 2lq+1)
#pragma unroll
    for (int mt = 0; mt < 4; ++mt) {
#pragma unroll
        for (int nt = 0; nt < 4; ++nt) {
            const float* c = acc[mt * 4 + nt];
            int row = bm + wm * 64 + mt * 16 + lr;
            int col = bn + wn * 32 + nt * 8 + 2 * lq;
            float b0 = bias[col], b1 = bias[col + 1];
            float2 v0 = make_float2(c[0] + b0, c[1] + b1);
            float2 v1 = make_float2(c[2] + b0, c[3] + b1);
            *(float2*)(C + (size_t)row * N + col)       = v0;
            *(float2*)(C + (size_t)(row + 8) * N + col) = v1;
        }
    }
}

// ---------------------------------------------------------------------------
// Attention: one block per (window n, head h, batch b). 256 threads.
// ---------------------------------------------------------------------------
__device__ __forceinline__ float rope_inv_freq(int j) {
    return (float)exp2(-(double)j * (13.287712379549449 / 32.0));
}

__global__ void __launch_bounds__(256) attn_kernel(
    const float* __restrict__ qkv,    // [B*L, 3H]
    const float* __restrict__ sinks,  // [NH, SINKS, DHEAD]
    float* __restrict__ Oout)         // [B*L, H]
{
    extern __shared__ float sm[];
    float* Qs = sm;                       // 64*TPAD
    float* Ts = sm + 64 * TPAD;           // 208*TPAD
    float* Ps = Ts + NKEY * TPAD;         // 64*PPAD

    const int n = blockIdx.x;
    const int h = blockIdx.y;
    const int b = blockIdx.z;
    const int tid = threadIdx.x;
    const float scale = 0.125f;

    // ---- load Q (RoPE + scale) ----
    for (int idx = tid; idx < 64 * 64; idx += 256) {
        int r  = idx >> 6;
        int dd = idx & 63;
        int l  = n * WIN + r;
        const float* qrow = qkv + (size_t)(b * LSEQ + l) * (3 * HID) + h * DHEAD;
        int j = dd & 31;
        float ang = (float)l * rope_inv_freq(j);
        float s, c;
        sincosf(ang, &s, &c);
        float x1 = qrow[j];
        float x2 = qrow[j + 32];
        float val = (dd < 32) ? (x1 * c - x2 * s) : (x1 * s + x2 * c);
        Qs[r * TPAD + dd] = val * scale;
    }
    // ---- sinks into Ts rows 0..15 ----
    for (int idx = tid; idx < SINKS * 64; idx += 256) {
        int r  = idx >> 6;
        int dd = idx & 63;
        Ts[r * TPAD + dd] = sinks[((size_t)h * SINKS + r) * DHEAD + dd];
    }
    // ---- K band (RoPE) into Ts rows 16..207 ----
    for (int idx = tid; idx < 3 * WIN * 64; idx += 256) {
        int kk = idx >> 6;
        int dd = idx & 63;
        int bn = n - 1 + kk / WIN;
        float val = 0.f;
        if (bn >= 0 && bn < NB) {
            int lk = bn * WIN + (kk & (WIN - 1));
            const float* krow = qkv + (size_t)(b * LSEQ + lk) * (3 * HID) + HID + h * DHEAD;
            int j = dd & 31;
            float ang = (float)lk * rope_inv_freq(j);
            float s, c;
            sincosf(ang, &s, &c);
            float x1 = krow[j];
            float x2 = krow[j + 32];
            val = (dd < 32) ? (x1 * c - x2 * s) : (x1 * s + x2 * c);
        }
        Ts[(SINKS + kk) * TPAD + dd] = val;
    }
    __syncthreads();

    // ---- scores ----
    const int qr   = tid >> 2;
    const int part = tid & 3;
    const int lq   = n * WIN + qr;
    const float* qrowS = Qs + qr * TPAD;

    for (int i = 0; i < NKEY / 4; ++i) {
        int kk = part + 4 * i;
        const float* trow = Ts + kk * TPAD;
        float s = 0.f;
#pragma unroll
        for (int d4 = 0; d4 < 16; ++d4) {
            float4 qv = *(const float4*)(qrowS + d4 * 4);
            float4 tv = *(const float4*)(trow + d4 * 4);
            s += qv.x * tv.x + qv.y * tv.y + qv.z * tv.z + qv.w * tv.w;
        }
        bool valid = true;
        if (kk >= SINKS) {
            int kb = kk - SINKS;
            int bn = n - 1 + kb / WIN;
            int lk = bn * WIN + (kb & (WIN - 1));
            valid = (bn >= 0) && (bn < NB) && (abs(lq - lk) <= WIN);
        }
        Ps[qr * PPAD + kk] = valid ? s : -1e30f;
    }

    // ---- softmax per row ----
    float mx = -1e30f;
    for (int i = 0; i < NKEY / 4; ++i)
        mx = fmaxf(mx, Ps[qr * PPAD + part + 4 * i]);
    mx = fmaxf(mx, __shfl_xor_sync(0xffffffffu, mx, 1));
    mx = fmaxf(mx, __shfl_xor_sync(0xffffffffu, mx, 2));
    float sum = 0.f;
    for (int i = 0; i < NKEY / 4; ++i) {
        float e = __expf(Ps[qr * PPAD + part + 4 * i] - mx);
        Ps[qr * PPAD + part + 4 * i] = e;
        sum += e;
    }
    sum += __shfl_xor_sync(0xffffffffu, sum, 1);
    sum += __shfl_xor_sync(0xffffffffu, sum, 2);
    float inv = 1.f / sum;
    for (int i = 0; i < NKEY / 4; ++i)
        Ps[qr * PPAD + part + 4 * i] *= inv;

    __syncthreads();

    // ---- V band ----
    for (int idx = tid; idx < 3 * WIN * 64; idx += 256) {
        int kk = idx >> 6;
        int dd = idx & 63;
        int bn = n - 1 + kk / WIN;
        float v = 0.f;
        if (bn >= 0 && bn < NB) {
            int lk = bn * WIN + (kk & (WIN - 1));
            v = qkv[(size_t)(b * LSEQ + lk) * (3 * HID) + 2 * HID + h * DHEAD + dd];
        }
        Ts[(SINKS + kk) * TPAD + dd] = v;
    }
    __syncthreads();

    // ---- O = P @ [sinks; Vband] ----
    const int dseg = part * 16;
    float accv[16];
#pragma unroll
    for (int j = 0; j < 16; ++j) accv[j] = 0.f;

    for (int k = 0; k < NKEY; ++k) {
        float p = Ps[qr * PPAD + k];
        const float* vrow = Ts + k * TPAD + dseg;
#pragma unroll
        for (int j4 = 0; j4 < 4; ++j4) {
            float4 vv = *(const float4*)(vrow + j4 * 4);
            accv[j4 * 4 + 0] += p * vv.x;
            accv[j4 * 4 + 1] += p * vv.y;
            accv[j4 * 4 + 2] += p * vv.z;
            accv[j4 * 4 + 3] += p * vv.w;
        }
    }

    float* orow = Oout + (size_t)(b * LSEQ + lq) * HID + h * DHEAD + dseg;
#pragma unroll
    for (int j4 = 0; j4 < 4; ++j4) {
        float4 o;
        o.x = accv[j4 * 4 + 0];
        o.y = accv[j4 * 4 + 1];
        o.z = accv[j4 * 4 + 2];
        o.w = accv[j4 * 4 + 3];
        *(float4*)(orow + j4 * 4) = o;
    }
}

// ---------------------------------------------------------------------------
extern "C" void kernel_launch(void* const* d_in, const int* in_sizes, int n_in,
                              void* d_out, int out_size)
{
    const float* u     = (const float*)d_in[0];
    const float* Wqkv  = (const float*)d_in[1];
    const float* bqkv  = (const float*)d_in[2];
    const float* Wo    = (const float*)d_in[3];
    const float* bo    = (const float*)d_in[4];
    const float* sinks = (const float*)d_in[5];
    float* y = (float*)d_out;

    void* p;
    cudaGetSymbolAddress(&p, g_qkv);
    float* qkv = (float*)p;
    cudaGetSymbolAddress(&p, g_att);
    float* att = (float*)p;

    const int M = BATCH * LSEQ;   // 8192

    // 1) qkv = u @ Wqkv^T + bqkv     [8192, 6144]
    {
        dim3 grid(3 * HID / 128, M / 128);
        tf32gemm_nt_bias<<<grid, 256>>>(u, Wqkv, bqkv, qkv, M, 3 * HID, DMODEL);
    }

    // 2) attention (RoPE fused)
    {
        const int smem = (64 * TPAD + NKEY * TPAD + 64 * PPAD) * (int)sizeof(float);
        cudaFuncSetAttribute(attn_kernel, cudaFuncAttributeMaxDynamicSharedMemorySize, smem);
        dim3 grid(NB, NH, BATCH);
        attn_kernel<<<grid, 256, smem>>>(qkv, sinks, att);
    }

    // 3) y = att @ Wo^T + bo         [8192, 2048]
    {
        dim3 grid(DMODEL / 128, M / 128);
        tf32gemm_nt_bias<<<grid, 256>>>(att, Wo, bo, y, M, DMODEL, HID);
    }
}